// round 15
// baseline (speedup 1.0000x reference)
#include <cuda_runtime.h>
#include <cuda_bf16.h>

// IMM (2-regime) Kalman filter, N=4096 particles x NT=400 steps, O=9 obs, L=4.
// One thread per particle; whole chain in registers. Low-rank structure of the
// loading matrices turns the 9x9 innovation solves into closed forms:
//   regime 2: rank-1 + diagonal  -> Sherman-Morrison
//   regime 1: rank-3 + diagonal with DIAGONAL W^T D^-1 W -> Woodbury w/ 3x3 inverse

#define NT_ 400
#define O_  9

__device__ float g_partial[512];

__global__ void __launch_bounds__(32, 1) imm_kf_kernel(
    const float* __restrict__ y,
    const float* __restrict__ B1s1,
    const float* __restrict__ B1s2,
    const float* __restrict__ l1f,
    const float* __restrict__ l2f,
    const float* __restrict__ logq,
    const float* __restrict__ logr,
    const float* __restrict__ gi,
    const float* __restrict__ gcoef,
    float* __restrict__ probs,
    float* __restrict__ ypred,
    int nTot)
{
    const int n = blockIdx.x * 32 + threadIdx.x;
    float ll = 0.0f;

    if (n < nTot) {
        // ---------------- data-independent constants ----------------
        float B1[3][3];
#pragma unroll
        for (int i = 0; i < 3; i++)
#pragma unroll
            for (int j = 0; j < 3; j++)
                B1[i][j] = B1s1[i * 3 + j];
        const float b2 = B1s2[0];

        float w[3][3];
#pragma unroll
        for (int j = 0; j < 3; j++) {
            w[j][0] = 1.0f;
            w[j][1] = l1f[2 * j];
            w[j][2] = l1f[2 * j + 1];
        }
        float bv[9];
        bv[0] = 1.0f;
#pragma unroll
        for (int o = 1; o < 9; o++) bv[o] = l2f[o - 1];

        float q[4];
#pragma unroll
        for (int i = 0; i < 4; i++) q[i] = expf(logq[i]);

        float r[9], dinv[9];
        float logdetD = 0.0f;
#pragma unroll
        for (int o = 0; o < 9; o++) {
            r[o] = expf(logr[o]);
            const float dd = r[o] + 1e-6f;     // F jitter
            dinv[o] = 1.0f / dd;
            logdetD += logf(dd);
        }

        // t1 = D^-1 W (block structure), g = diag(W^T D^-1 W), h1 = diag(T^T R T)
        float t1[3][3], g[3], h1[3];
#pragma unroll
        for (int j = 0; j < 3; j++) {
            g[j] = 0.0f; h1[j] = 0.0f;
#pragma unroll
            for (int k = 0; k < 3; k++) {
                t1[j][k] = w[j][k] * dinv[3 * j + k];
                g[j]  += w[j][k] * t1[j][k];
                h1[j] += t1[j][k] * t1[j][k] * r[3 * j + k];
            }
        }
        float tb[9], g2 = 0.0f, h2 = 0.0f;
#pragma unroll
        for (int o = 0; o < 9; o++) {
            tb[o] = bv[o] * dinv[o];
            g2 += bv[o] * tb[o];
            h2 += tb[o] * tb[o] * r[o];
        }

        const float gam0 = gi[0];
        const float gc0 = gcoef[0], gc1 = gcoef[1], gc2 = gcoef[2];
        const float LLC = -0.5f * 9.0f * 1.8378770664093453f;  // -0.5*O*log(2pi)

        // ---------------- state ----------------
        float pr1 = 0.99f, pr2 = 0.01f;
        float eta[4] = {0.0f, 0.0f, 0.0f, 0.0f};
        float P[4][4];
#pragma unroll
        for (int i = 0; i < 4; i++)
#pragma unroll
            for (int j = 0; j < 4; j++)
                P[i][j] = (i == j) ? 1000.0f : 0.0f;

        const float* yrow = y + (size_t)n * NT_ * O_;
        float* pout = probs + (size_t)n * NT_ * 2;
        float* yout = ypred + (size_t)n * NT_ * O_;

        // software-pipelined y prefetch (one step ahead)
        float ynext[9];
#pragma unroll
        for (int o = 0; o < 9; o++) ynext[o] = yrow[o];

#pragma unroll 1
        for (int t = 0; t < NT_; t++) {
            float yc[9];
#pragma unroll
            for (int o = 0; o < 9; o++) yc[o] = ynext[o];
            {
                const float* ynp = yrow + (size_t)((t + 1 < NT_) ? (t + 1) : t) * O_;
#pragma unroll
                for (int o = 0; o < 9; o++) ynext[o] = ynp[o];
            }

            // ---- regime-1 stay probability ----
            const float xg = gam0 + eta[0] * gc0 + eta[1] * gc1 + eta[2] * gc2;
            const float p11 = 1.0f / (1.0f + expf(-xg));

            // ---- prediction: eta_pred = B eta ; P_pred = B P B^T + Q ----
            float ep[4];
            ep[0] = B1[0][0] * eta[0] + B1[0][1] * eta[1] + B1[0][2] * eta[2];
            ep[1] = B1[1][0] * eta[0] + B1[1][1] * eta[1] + B1[1][2] * eta[2];
            ep[2] = B1[2][0] * eta[0] + B1[2][1] * eta[1] + B1[2][2] * eta[2];
            ep[3] = b2 * eta[3];

            float U[4][4];
#pragma unroll
            for (int l = 0; l < 4; l++) {
                U[0][l] = B1[0][0] * P[0][l] + B1[0][1] * P[1][l] + B1[0][2] * P[2][l];
                U[1][l] = B1[1][0] * P[0][l] + B1[1][1] * P[1][l] + B1[1][2] * P[2][l];
                U[2][l] = B1[2][0] * P[0][l] + B1[2][1] * P[1][l] + B1[2][2] * P[2][l];
                U[3][l] = b2 * P[3][l];
            }
            float Pp[4][4];
#pragma unroll
            for (int i = 0; i < 4; i++) {
                Pp[i][0] = U[i][0] * B1[0][0] + U[i][1] * B1[0][1] + U[i][2] * B1[0][2];
                Pp[i][1] = U[i][0] * B1[1][0] + U[i][1] * B1[1][1] + U[i][2] * B1[1][2];
                Pp[i][2] = U[i][0] * B1[2][0] + U[i][1] * B1[2][1] + U[i][2] * B1[2][2];
                Pp[i][3] = U[i][3] * b2;
            }
            Pp[0][0] += q[0]; Pp[1][1] += q[1]; Pp[2][2] += q[2]; Pp[3][3] += q[3];

            // ================= regime 2 (rank-1 + diag) =================
            const float s2 = Pp[3][3];
            float v2[9];
#pragma unroll
            for (int o = 0; o < 9; o++) v2[o] = yc[o] - bv[o] * ep[3];
            float vdv2 = 0.0f, tv = 0.0f;
#pragma unroll
            for (int o = 0; o < 9; o++) {
                vdv2 += v2[o] * v2[o] * dinv[o];
                tv   += tb[o] * v2[o];
            }
            const float den  = 1.0f + s2 * g2;
            const float rden = 1.0f / den;
            const float ll2 = LLC - 0.5f * (logdetD + logf(den))
                                  - 0.5f * (vdv2 - s2 * tv * tv * rden);
            const float kv  = tv * rden;
            float p3r[4];
#pragma unroll
            for (int i = 0; i < 4; i++) p3r[i] = Pp[3][i];
            float eta2[4];
#pragma unroll
            for (int i = 0; i < 4; i++) eta2[i] = ep[i] + p3r[i] * kv;
            const float c2s = g2 * rden;
            const float krk = h2 * rden * rden;
            float cp[4];
#pragma unroll
            for (int i = 0; i < 4; i++) cp[i] = c2s * p3r[i];
            float AP2[4][4];
#pragma unroll
            for (int i = 0; i < 4; i++)
#pragma unroll
                for (int l = 0; l < 4; l++)
                    AP2[i][l] = Pp[i][l] - cp[i] * Pp[3][l];
            float P2[4][4];
#pragma unroll
            for (int i = 0; i < 4; i++) {
                const float kp = krk * p3r[i];
#pragma unroll
                for (int l = 0; l < 4; l++)
                    P2[i][l] = AP2[i][l] - AP2[i][3] * cp[l] + kp * p3r[l];
            }

            // ================= regime 1 (rank-3 + diag, Woodbury) =================
            float v1[9];
#pragma unroll
            for (int j = 0; j < 3; j++)
#pragma unroll
                for (int k = 0; k < 3; k++)
                    v1[3 * j + k] = yc[3 * j + k] - w[j][k] * ep[j];
            float vdv1 = 0.0f;
#pragma unroll
            for (int o = 0; o < 9; o++) vdv1 += v1[o] * v1[o] * dinv[o];
            float cc[3];
#pragma unroll
            for (int j = 0; j < 3; j++)
                cc[j] = t1[j][0] * v1[3 * j] + t1[j][1] * v1[3 * j + 1] + t1[j][2] * v1[3 * j + 2];

            // M = I + S*diag(g), S = Pp[0:3,0:3]
            const float M00 = 1.0f + Pp[0][0] * g[0], M01 = Pp[0][1] * g[1], M02 = Pp[0][2] * g[2];
            const float M10 = Pp[1][0] * g[0], M11 = 1.0f + Pp[1][1] * g[1], M12 = Pp[1][2] * g[2];
            const float M20 = Pp[2][0] * g[0], M21 = Pp[2][1] * g[1], M22 = 1.0f + Pp[2][2] * g[2];
            const float co00 = M11 * M22 - M12 * M21;
            const float co01 = M12 * M20 - M10 * M22;
            const float co02 = M10 * M21 - M11 * M20;
            const float detM = M00 * co00 + M01 * co01 + M02 * co02;
            const float rdet = 1.0f / detM;
            float Mi[3][3];
            Mi[0][0] = co00 * rdet;
            Mi[0][1] = (M02 * M21 - M01 * M22) * rdet;
            Mi[0][2] = (M01 * M12 - M02 * M11) * rdet;
            Mi[1][0] = co01 * rdet;
            Mi[1][1] = (M00 * M22 - M02 * M20) * rdet;
            Mi[1][2] = (M02 * M10 - M00 * M12) * rdet;
            Mi[2][0] = co02 * rdet;
            Mi[2][1] = (M01 * M20 - M00 * M21) * rdet;
            Mi[2][2] = (M00 * M11 - M01 * M10) * rdet;

            // N = M^-1 S   ( = (S^-1 + G)^-1 ), F^-1 = D^-1 - T N T^T
            float Nm[3][3];
#pragma unroll
            for (int i = 0; i < 3; i++)
#pragma unroll
                for (int j2 = 0; j2 < 3; j2++)
                    Nm[i][j2] = Mi[i][0] * Pp[0][j2] + Mi[i][1] * Pp[1][j2] + Mi[i][2] * Pp[2][j2];
            float quadsub = 0.0f;
#pragma unroll
            for (int i = 0; i < 3; i++)
                quadsub += cc[i] * (Nm[i][0] * cc[0] + Nm[i][1] * cc[1] + Nm[i][2] * cc[2]);
            const float ll1 = LLC - 0.5f * (logdetD + logf(detM))
                                  - 0.5f * (vdv1 - quadsub);

            // K[i, 3j+k] = C[j][i] * t1[j][k],  C = Hr - (N G) Hr,  Hr = rows 0..2 of Pp
            float Ng[3][3];
#pragma unroll
            for (int j = 0; j < 3; j++)
#pragma unroll
                for (int m = 0; m < 3; m++)
                    Ng[j][m] = Nm[j][m] * g[m];
            float C[3][4];
#pragma unroll
            for (int j = 0; j < 3; j++)
#pragma unroll
                for (int i = 0; i < 4; i++)
                    C[j][i] = Pp[j][i] - (Ng[j][0] * Pp[0][i] + Ng[j][1] * Pp[1][i] + Ng[j][2] * Pp[2][i]);
            float eta1[4];
#pragma unroll
            for (int i = 0; i < 4; i++)
                eta1[i] = ep[i] + C[0][i] * cc[0] + C[1][i] * cc[1] + C[2][i] * cc[2];

            float Cg[3][4];
#pragma unroll
            for (int m = 0; m < 3; m++)
#pragma unroll
                for (int i = 0; i < 4; i++)
                    Cg[m][i] = C[m][i] * g[m];
            float AP1[4][4];
#pragma unroll
            for (int i = 0; i < 4; i++)
#pragma unroll
                for (int l = 0; l < 4; l++)
                    AP1[i][l] = Pp[i][l] - (Cg[0][i] * Pp[0][l] + Cg[1][i] * Pp[1][l] + Cg[2][i] * Pp[2][l]);
            float Ch[3][4];
#pragma unroll
            for (int j = 0; j < 3; j++)
#pragma unroll
                for (int i = 0; i < 4; i++)
                    Ch[j][i] = C[j][i] * h1[j];
            float P1[4][4];
#pragma unroll
            for (int i = 0; i < 4; i++)
#pragma unroll
                for (int l = 0; l < 4; l++)
                    P1[i][l] = AP1[i][l]
                             - (AP1[i][0] * Cg[0][l] + AP1[i][1] * Cg[1][l] + AP1[i][2] * Cg[2][l])
                             + (Ch[0][i] * C[0][l] + Ch[1][i] * C[1][l] + Ch[2][i] * C[2][l]);

            // ================= IMM mixing (exact reference arithmetic) =================
            const float e1 = expf(ll1), e2 = expf(ll2);
            const float num1 = e1 * (pr1 * p11);
            const float num2 = e2 * (pr1 * (1.0f - p11) + pr2);
            const float marg = num1 + num2 + 1e-9f;
            ll += logf(marg);
            const float rmarg = 1.0f / marg;
            pr1 = num1 * rmarg;
            pr2 = num2 * rmarg;

            float etat[4], d1v[4], d2v[4];
#pragma unroll
            for (int i = 0; i < 4; i++) {
                etat[i] = pr1 * eta1[i] + pr2 * eta2[i];
                d1v[i]  = eta1[i] - etat[i];
                d2v[i]  = eta2[i] - etat[i];
            }
            float Pt[4][4];
#pragma unroll
            for (int i = 0; i < 4; i++)
#pragma unroll
                for (int l = 0; l < 4; l++)
                    Pt[i][l] = pr1 * (P1[i][l] + d1v[i] * d1v[l])
                             + pr2 * (P2[i][l] + d2v[i] * d2v[l]);
#pragma unroll
            for (int i = 0; i < 4; i++) {
                eta[i] = etat[i];
#pragma unroll
                for (int l = 0; l < 4; l++)
                    P[i][l] = 0.5f * (Pt[i][l] + Pt[l][i]);
            }

            // ---- outputs ----
            pout[t * 2 + 0] = pr1;
            pout[t * 2 + 1] = pr2;
            const float pe3 = pr2 * etat[3];
#pragma unroll
            for (int j = 0; j < 3; j++)
#pragma unroll
                for (int k = 0; k < 3; k++) {
                    const int o = 3 * j + k;
                    yout[t * 9 + o] = pr1 * (w[j][k] * etat[j]) + bv[o] * pe3;
                }
        }
    }

    // deterministic per-block partial for the NLL
#pragma unroll
    for (int off = 16; off > 0; off >>= 1)
        ll += __shfl_xor_sync(0xffffffffu, ll, off);
    if (threadIdx.x == 0) g_partial[blockIdx.x] = ll;
}

__global__ void nll_reduce_kernel(float* __restrict__ out, int nb)
{
    // single thread, fixed summation order -> deterministic
    float s = 0.0f;
    for (int i = 0; i < nb; i++) s += g_partial[i];
    out[0] = -s;
}

extern "C" void kernel_launch(void* const* d_in, const int* in_sizes, int n_in,
                              void* d_out, int out_size)
{
    const float* y     = (const float*)d_in[0];
    const float* B1s1  = (const float*)d_in[1];
    const float* B1s2  = (const float*)d_in[2];
    const float* l1f   = (const float*)d_in[3];
    const float* l2f   = (const float*)d_in[4];
    const float* logq  = (const float*)d_in[5];
    const float* logr  = (const float*)d_in[6];
    const float* gi    = (const float*)d_in[7];
    const float* gcoef = (const float*)d_in[8];

    const int nTot = in_sizes[0] / (NT_ * O_);   // 4096

    float* out   = (float*)d_out;
    float* probs = out + 1;
    float* ypred = out + 1 + (size_t)nTot * NT_ * 2;

    const int grid = (nTot + 31) / 32;           // 128 blocks of 1 warp -> max SM spread
    imm_kf_kernel<<<grid, 32>>>(y, B1s1, B1s2, l1f, l2f, logq, logr, gi, gcoef,
                                probs, ypred, nTot);
    nll_reduce_kernel<<<1, 1>>>(out, grid);
}

// round 16
// speedup vs baseline: 1.1215x; 1.1215x over previous
#include <cuda_runtime.h>
#include <cuda_bf16.h>

// IMM (2-regime) Kalman filter, N=4096 particles x NT=400 steps, O=9 obs, L=4.
// One thread per particle; whole chain in registers.
//   regime 2: rank-1 + diagonal -> Sherman-Morrison; Joseph form collapses to
//             P2 = Pp - beta * p3 p3^T (scalar beta)
//   regime 1: rank-3 + diagonal with DIAGONAL W^T D^-1 W -> Woodbury w/ 3x3 inverse
// All symmetric matrices computed upper-triangle-only; fast MUFU transcendentals.

#define NT_ 400
#define O_  9

__device__ float g_partial[512];

__global__ void __launch_bounds__(32, 1) imm_kf_kernel(
    const float* __restrict__ y,
    const float* __restrict__ B1s1,
    const float* __restrict__ B1s2,
    const float* __restrict__ l1f,
    const float* __restrict__ l2f,
    const float* __restrict__ logq,
    const float* __restrict__ logr,
    const float* __restrict__ gi,
    const float* __restrict__ gcoef,
    float* __restrict__ probs,
    float* __restrict__ ypred,
    int nTot)
{
    const int n = blockIdx.x * 32 + threadIdx.x;
    float ll = 0.0f;

    if (n < nTot) {
        // ---------------- data-independent constants ----------------
        float B1[3][3];
#pragma unroll
        for (int i = 0; i < 3; i++)
#pragma unroll
            for (int j = 0; j < 3; j++)
                B1[i][j] = B1s1[i * 3 + j];
        const float b2 = B1s2[0];

        float w[3][3];
#pragma unroll
        for (int j = 0; j < 3; j++) {
            w[j][0] = 1.0f;
            w[j][1] = l1f[2 * j];
            w[j][2] = l1f[2 * j + 1];
        }
        float bv[9];
        bv[0] = 1.0f;
#pragma unroll
        for (int o = 1; o < 9; o++) bv[o] = l2f[o - 1];

        float q[4];
#pragma unroll
        for (int i = 0; i < 4; i++) q[i] = expf(logq[i]);

        float r[9], dinv[9];
        float logdetD = 0.0f;
#pragma unroll
        for (int o = 0; o < 9; o++) {
            r[o] = expf(logr[o]);
            const float dd = r[o] + 1e-6f;     // F jitter
            dinv[o] = 1.0f / dd;
            logdetD += logf(dd);
        }

        // t1 = D^-1 W (block structure), g = diag(W^T D^-1 W), h1 = diag(T^T R T)
        float t1[3][3], g[3], h1[3];
#pragma unroll
        for (int j = 0; j < 3; j++) {
            g[j] = 0.0f; h1[j] = 0.0f;
#pragma unroll
            for (int k = 0; k < 3; k++) {
                t1[j][k] = w[j][k] * dinv[3 * j + k];
                g[j]  += w[j][k] * t1[j][k];
                h1[j] += t1[j][k] * t1[j][k] * r[3 * j + k];
            }
        }
        float tb[9], g2 = 0.0f, h2 = 0.0f;
#pragma unroll
        for (int o = 0; o < 9; o++) {
            tb[o] = bv[o] * dinv[o];
            g2 += bv[o] * tb[o];
            h2 += tb[o] * tb[o] * r[o];
        }

        const float gam0 = gi[0];
        const float gc0 = gcoef[0], gc1 = gcoef[1], gc2 = gcoef[2];
        const float LLC = -0.5f * 9.0f * 1.8378770664093453f;  // -0.5*O*log(2pi)

        // ---------------- state ----------------
        float pr1 = 0.99f, pr2 = 0.01f;
        float eta[4] = {0.0f, 0.0f, 0.0f, 0.0f};
        float P[4][4];
#pragma unroll
        for (int i = 0; i < 4; i++)
#pragma unroll
            for (int j = 0; j < 4; j++)
                P[i][j] = (i == j) ? 1000.0f : 0.0f;

        const float* yrow = y + (size_t)n * NT_ * O_;
        float* pout = probs + (size_t)n * NT_ * 2;
        float* yout = ypred + (size_t)n * NT_ * O_;

        // software-pipelined y prefetch (one step ahead)
        float ynext[9];
#pragma unroll
        for (int o = 0; o < 9; o++) ynext[o] = yrow[o];

#pragma unroll 1
        for (int t = 0; t < NT_; t++) {
            float yc[9];
#pragma unroll
            for (int o = 0; o < 9; o++) yc[o] = ynext[o];
            {
                const float* ynp = yrow + (size_t)((t + 1 < NT_) ? (t + 1) : t) * O_;
#pragma unroll
                for (int o = 0; o < 9; o++) ynext[o] = ynp[o];
            }

            // ---- regime-1 stay probability ----
            const float xg = fmaf(eta[2], gc2, fmaf(eta[1], gc1, fmaf(eta[0], gc0, gam0)));
            const float p11 = __fdividef(1.0f, 1.0f + __expf(-xg));

            // ---- prediction: eta_pred = B eta ; P_pred = B P B^T + Q (upper) ----
            float ep[4];
            ep[0] = B1[0][0] * eta[0] + B1[0][1] * eta[1] + B1[0][2] * eta[2];
            ep[1] = B1[1][0] * eta[0] + B1[1][1] * eta[1] + B1[1][2] * eta[2];
            ep[2] = B1[2][0] * eta[0] + B1[2][1] * eta[1] + B1[2][2] * eta[2];
            ep[3] = b2 * eta[3];

            float U[4][4];
#pragma unroll
            for (int l = 0; l < 4; l++) {
                U[0][l] = B1[0][0] * P[0][l] + B1[0][1] * P[1][l] + B1[0][2] * P[2][l];
                U[1][l] = B1[1][0] * P[0][l] + B1[1][1] * P[1][l] + B1[1][2] * P[2][l];
                U[2][l] = B1[2][0] * P[0][l] + B1[2][1] * P[1][l] + B1[2][2] * P[2][l];
                U[3][l] = b2 * P[3][l];
            }
            float Pp[4][4];
#pragma unroll
            for (int i = 0; i < 4; i++)
#pragma unroll
                for (int l = i; l < 4; l++) {
                    Pp[i][l] = (l < 3)
                        ? (U[i][0] * B1[l][0] + U[i][1] * B1[l][1] + U[i][2] * B1[l][2])
                        : (U[i][3] * b2);
                    Pp[l][i] = Pp[i][l];                 // mirror (register alias)
                }
            Pp[0][0] += q[0]; Pp[1][1] += q[1]; Pp[2][2] += q[2]; Pp[3][3] += q[3];

            // ================= regime 2 (rank-1 + diag) =================
            const float s2 = Pp[3][3];
            float v2[9];
#pragma unroll
            for (int o = 0; o < 9; o++) v2[o] = yc[o] - bv[o] * ep[3];
            float vdv2 = 0.0f, tv = 0.0f;
#pragma unroll
            for (int o = 0; o < 9; o++) {
                vdv2 += v2[o] * v2[o] * dinv[o];
                tv   += tb[o] * v2[o];
            }
            const float den  = 1.0f + s2 * g2;
            const float rden = __fdividef(1.0f, den);
            const float ll2 = LLC - 0.5f * (logdetD + __logf(den))
                                  - 0.5f * (vdv2 - s2 * tv * tv * rden);
            const float kv  = tv * rden;
            float p3r[4];
#pragma unroll
            for (int i = 0; i < 4; i++) p3r[i] = Pp[i][3];
            float eta2[4];
#pragma unroll
            for (int i = 0; i < 4; i++) eta2[i] = ep[i] + p3r[i] * kv;
            // Joseph form collapses exactly: P2 = Pp - beta * p3 p3^T
            const float c2s  = g2 * rden;
            const float krk  = h2 * rden * rden;
            const float beta = c2s * (1.0f + rden) - krk;
            float bp[4];
#pragma unroll
            for (int i = 0; i < 4; i++) bp[i] = beta * p3r[i];
            float P2u[4][4];
#pragma unroll
            for (int i = 0; i < 4; i++)
#pragma unroll
                for (int l = i; l < 4; l++)
                    P2u[i][l] = Pp[i][l] - bp[i] * p3r[l];

            // ================= regime 1 (rank-3 + diag, Woodbury) =================
            float v1[9];
#pragma unroll
            for (int j = 0; j < 3; j++)
#pragma unroll
                for (int k = 0; k < 3; k++)
                    v1[3 * j + k] = yc[3 * j + k] - w[j][k] * ep[j];
            float vdv1 = 0.0f;
#pragma unroll
            for (int o = 0; o < 9; o++) vdv1 += v1[o] * v1[o] * dinv[o];
            float cc[3];
#pragma unroll
            for (int j = 0; j < 3; j++)
                cc[j] = t1[j][0] * v1[3 * j] + t1[j][1] * v1[3 * j + 1] + t1[j][2] * v1[3 * j + 2];

            // M = I + S*diag(g), S = Pp[0:3,0:3]
            const float M00 = 1.0f + Pp[0][0] * g[0], M01 = Pp[0][1] * g[1], M02 = Pp[0][2] * g[2];
            const float M10 = Pp[1][0] * g[0], M11 = 1.0f + Pp[1][1] * g[1], M12 = Pp[1][2] * g[2];
            const float M20 = Pp[2][0] * g[0], M21 = Pp[2][1] * g[1], M22 = 1.0f + Pp[2][2] * g[2];
            const float co00 = M11 * M22 - M12 * M21;
            const float co01 = M12 * M20 - M10 * M22;
            const float co02 = M10 * M21 - M11 * M20;
            const float detM = M00 * co00 + M01 * co01 + M02 * co02;
            const float rdet = __fdividef(1.0f, detM);
            float Mi[3][3];
            Mi[0][0] = co00 * rdet;
            Mi[0][1] = (M02 * M21 - M01 * M22) * rdet;
            Mi[0][2] = (M01 * M12 - M02 * M11) * rdet;
            Mi[1][0] = co01 * rdet;
            Mi[1][1] = (M00 * M22 - M02 * M20) * rdet;
            Mi[1][2] = (M02 * M10 - M00 * M12) * rdet;
            Mi[2][0] = co02 * rdet;
            Mi[2][1] = (M01 * M20 - M00 * M21) * rdet;
            Mi[2][2] = (M00 * M11 - M01 * M10) * rdet;

            // N = M^-1 S
            float Nm[3][3];
#pragma unroll
            for (int i = 0; i < 3; i++)
#pragma unroll
                for (int j2 = 0; j2 < 3; j2++)
                    Nm[i][j2] = Mi[i][0] * Pp[0][j2] + Mi[i][1] * Pp[1][j2] + Mi[i][2] * Pp[2][j2];
            float quadsub = 0.0f;
#pragma unroll
            for (int i = 0; i < 3; i++)
                quadsub += cc[i] * (Nm[i][0] * cc[0] + Nm[i][1] * cc[1] + Nm[i][2] * cc[2]);
            const float ll1 = LLC - 0.5f * (logdetD + __logf(detM))
                                  - 0.5f * (vdv1 - quadsub);

            // K[i, 3j+k] = C[j][i] * t1[j][k],  C = Hr - (N G) Hr
            float Ng[3][3];
#pragma unroll
            for (int j = 0; j < 3; j++)
#pragma unroll
                for (int m = 0; m < 3; m++)
                    Ng[j][m] = Nm[j][m] * g[m];
            float C[3][4];
#pragma unroll
            for (int j = 0; j < 3; j++)
#pragma unroll
                for (int i = 0; i < 4; i++)
                    C[j][i] = Pp[j][i] - (Ng[j][0] * Pp[0][i] + Ng[j][1] * Pp[1][i] + Ng[j][2] * Pp[2][i]);
            float eta1[4];
#pragma unroll
            for (int i = 0; i < 4; i++)
                eta1[i] = ep[i] + C[0][i] * cc[0] + C[1][i] * cc[1] + C[2][i] * cc[2];

            float Cg[3][4];
#pragma unroll
            for (int m = 0; m < 3; m++)
#pragma unroll
                for (int i = 0; i < 4; i++)
                    Cg[m][i] = C[m][i] * g[m];
            float AP1[4][4];
#pragma unroll
            for (int i = 0; i < 4; i++)
#pragma unroll
                for (int l = 0; l < 4; l++)
                    AP1[i][l] = Pp[i][l] - (Cg[0][i] * Pp[0][l] + Cg[1][i] * Pp[1][l] + Cg[2][i] * Pp[2][l]);
            float Ch[3][4];
#pragma unroll
            for (int j = 0; j < 3; j++)
#pragma unroll
                for (int i = 0; i < 4; i++)
                    Ch[j][i] = C[j][i] * h1[j];
            float P1u[4][4];   // Joseph form, upper triangle only (exactly symmetric)
#pragma unroll
            for (int i = 0; i < 4; i++)
#pragma unroll
                for (int l = i; l < 4; l++)
                    P1u[i][l] = AP1[i][l]
                              - (AP1[i][0] * Cg[0][l] + AP1[i][1] * Cg[1][l] + AP1[i][2] * Cg[2][l])
                              + (Ch[0][i] * C[0][l] + Ch[1][i] * C[1][l] + Ch[2][i] * C[2][l]);

            // ================= IMM mixing (reference EPS arithmetic) =================
            const float e1 = __expf(ll1), e2 = __expf(ll2);
            const float num1 = e1 * (pr1 * p11);
            const float num2 = e2 * (pr1 * (1.0f - p11) + pr2);
            const float marg = num1 + num2 + 1e-9f;
            ll += __logf(marg);
            const float rmarg = __fdividef(1.0f, marg);
            pr1 = num1 * rmarg;
            pr2 = num2 * rmarg;

            float etat[4], d1v[4], d2v[4];
#pragma unroll
            for (int i = 0; i < 4; i++) {
                etat[i] = pr1 * eta1[i] + pr2 * eta2[i];
                d1v[i]  = eta1[i] - etat[i];
                d2v[i]  = eta2[i] - etat[i];
            }
#pragma unroll
            for (int i = 0; i < 4; i++) {
                eta[i] = etat[i];
#pragma unroll
                for (int l = i; l < 4; l++) {
                    const float pt = pr1 * (P1u[i][l] + d1v[i] * d1v[l])
                                   + pr2 * (P2u[i][l] + d2v[i] * d2v[l]);
                    P[i][l] = pt;
                    P[l][i] = pt;
                }
            }

            // ---- outputs ----
            pout[t * 2 + 0] = pr1;
            pout[t * 2 + 1] = pr2;
            const float pe3 = pr2 * etat[3];
#pragma unroll
            for (int j = 0; j < 3; j++)
#pragma unroll
                for (int k = 0; k < 3; k++) {
                    const int o = 3 * j + k;
                    yout[t * 9 + o] = pr1 * (w[j][k] * etat[j]) + bv[o] * pe3;
                }
        }
    }

    // deterministic per-block partial for the NLL
#pragma unroll
    for (int off = 16; off > 0; off >>= 1)
        ll += __shfl_xor_sync(0xffffffffu, ll, off);
    if (threadIdx.x == 0) g_partial[blockIdx.x] = ll;
}

__global__ void nll_reduce_kernel(float* __restrict__ out, int nb)
{
    // one warp, fixed strided order + fixed shuffle tree -> deterministic
    const int t = threadIdx.x;
    float s = 0.0f;
    for (int i = t; i < nb; i += 32) s += g_partial[i];
#pragma unroll
    for (int off = 16; off > 0; off >>= 1)
        s += __shfl_xor_sync(0xffffffffu, s, off);
    if (t == 0) out[0] = -s;
}

extern "C" void kernel_launch(void* const* d_in, const int* in_sizes, int n_in,
                              void* d_out, int out_size)
{
    const float* y     = (const float*)d_in[0];
    const float* B1s1  = (const float*)d_in[1];
    const float* B1s2  = (const float*)d_in[2];
    const float* l1f   = (const float*)d_in[3];
    const float* l2f   = (const float*)d_in[4];
    const float* logq  = (const float*)d_in[5];
    const float* logr  = (const float*)d_in[6];
    const float* gi    = (const float*)d_in[7];
    const float* gcoef = (const float*)d_in[8];

    const int nTot = in_sizes[0] / (NT_ * O_);   // 4096

    float* out   = (float*)d_out;
    float* probs = out + 1;
    float* ypred = out + 1 + (size_t)nTot * NT_ * 2;

    const int grid = (nTot + 31) / 32;           // 128 blocks of 1 warp -> max SM spread
    imm_kf_kernel<<<grid, 32>>>(y, B1s1, B1s2, l1f, l2f, logq, logr, gi, gcoef,
                                probs, ypred, nTot);
    nll_reduce_kernel<<<1, 32>>>(out, grid);
}

// round 17
// speedup vs baseline: 1.1270x; 1.0049x over previous
#include <cuda_runtime.h>
#include <cuda_bf16.h>

// IMM (2-regime) Kalman filter, N=4096 particles x NT=400 steps, O=9 obs, L=4.
// One thread per particle; whole chain in registers.
//   regime 2: rank-1 + diagonal -> Sherman-Morrison; optimal-gain identity gives
//             P2 = Pp - c2s * p3 p3^T
//   regime 1: rank-3 + diagonal with DIAGONAL W^T D^-1 W -> Woodbury w/ 3x3 inverse;
//             optimal-gain identity gives P1 = Pp - sum_j Cg[j] (x) Pp_row_j
// (Joseph form == simple form exactly for the optimal K; filter is exponentially
//  stable so the fp-trajectory difference decays.)
// Symmetric matrices computed upper-triangle-only; fast MUFU transcendentals.

#define NT_ 400
#define O_  9

__device__ float g_partial[512];

__global__ void __launch_bounds__(32, 1) imm_kf_kernel(
    const float* __restrict__ y,
    const float* __restrict__ B1s1,
    const float* __restrict__ B1s2,
    const float* __restrict__ l1f,
    const float* __restrict__ l2f,
    const float* __restrict__ logq,
    const float* __restrict__ logr,
    const float* __restrict__ gi,
    const float* __restrict__ gcoef,
    float* __restrict__ probs,
    float* __restrict__ ypred,
    int nTot)
{
    const int n = blockIdx.x * 32 + threadIdx.x;
    float ll = 0.0f;

    if (n < nTot) {
        // ---------------- data-independent constants ----------------
        float B1[3][3];
#pragma unroll
        for (int i = 0; i < 3; i++)
#pragma unroll
            for (int j = 0; j < 3; j++)
                B1[i][j] = B1s1[i * 3 + j];
        const float b2 = B1s2[0];

        float w[3][3];
#pragma unroll
        for (int j = 0; j < 3; j++) {
            w[j][0] = 1.0f;
            w[j][1] = l1f[2 * j];
            w[j][2] = l1f[2 * j + 1];
        }
        float bv[9];
        bv[0] = 1.0f;
#pragma unroll
        for (int o = 1; o < 9; o++) bv[o] = l2f[o - 1];

        float q[4];
#pragma unroll
        for (int i = 0; i < 4; i++) q[i] = expf(logq[i]);

        float r[9], dinv[9];
        float logdetD = 0.0f;
#pragma unroll
        for (int o = 0; o < 9; o++) {
            r[o] = expf(logr[o]);
            const float dd = r[o] + 1e-6f;     // F jitter
            dinv[o] = 1.0f / dd;
            logdetD += logf(dd);
        }

        // t1 = D^-1 W (block structure), g = diag(W^T D^-1 W)
        float t1[3][3], g[3];
#pragma unroll
        for (int j = 0; j < 3; j++) {
            g[j] = 0.0f;
#pragma unroll
            for (int k = 0; k < 3; k++) {
                t1[j][k] = w[j][k] * dinv[3 * j + k];
                g[j]  += w[j][k] * t1[j][k];
            }
        }
        float tb[9], g2 = 0.0f;
#pragma unroll
        for (int o = 0; o < 9; o++) {
            tb[o] = bv[o] * dinv[o];
            g2 += bv[o] * tb[o];
        }

        const float gam0 = gi[0];
        const float gc0 = gcoef[0], gc1 = gcoef[1], gc2 = gcoef[2];
        const float LLC = -0.5f * 9.0f * 1.8378770664093453f;  // -0.5*O*log(2pi)

        // ---------------- state ----------------
        float pr1 = 0.99f, pr2 = 0.01f;
        float eta[4] = {0.0f, 0.0f, 0.0f, 0.0f};
        float P[4][4];
#pragma unroll
        for (int i = 0; i < 4; i++)
#pragma unroll
            for (int j = 0; j < 4; j++)
                P[i][j] = (i == j) ? 1000.0f : 0.0f;

        const float* yrow = y + (size_t)n * NT_ * O_;
        float* pout = probs + (size_t)n * NT_ * 2;
        float* yout = ypred + (size_t)n * NT_ * O_;

        // software-pipelined y prefetch (one step ahead)
        float ynext[9];
#pragma unroll
        for (int o = 0; o < 9; o++) ynext[o] = yrow[o];

#pragma unroll 1
        for (int t = 0; t < NT_; t++) {
            float yc[9];
#pragma unroll
            for (int o = 0; o < 9; o++) yc[o] = ynext[o];
            {
                const float* ynp = yrow + (size_t)((t + 1 < NT_) ? (t + 1) : t) * O_;
#pragma unroll
                for (int o = 0; o < 9; o++) ynext[o] = ynp[o];
            }

            // ---- regime-1 stay probability ----
            const float xg = fmaf(eta[2], gc2, fmaf(eta[1], gc1, fmaf(eta[0], gc0, gam0)));
            const float p11 = __fdividef(1.0f, 1.0f + __expf(-xg));

            // ---- prediction: eta_pred = B eta ; P_pred = B P B^T + Q (upper) ----
            float ep[4];
            ep[0] = B1[0][0] * eta[0] + B1[0][1] * eta[1] + B1[0][2] * eta[2];
            ep[1] = B1[1][0] * eta[0] + B1[1][1] * eta[1] + B1[1][2] * eta[2];
            ep[2] = B1[2][0] * eta[0] + B1[2][1] * eta[1] + B1[2][2] * eta[2];
            ep[3] = b2 * eta[3];

            float U[4][4];
#pragma unroll
            for (int l = 0; l < 4; l++) {
                U[0][l] = B1[0][0] * P[0][l] + B1[0][1] * P[1][l] + B1[0][2] * P[2][l];
                U[1][l] = B1[1][0] * P[0][l] + B1[1][1] * P[1][l] + B1[1][2] * P[2][l];
                U[2][l] = B1[2][0] * P[0][l] + B1[2][1] * P[1][l] + B1[2][2] * P[2][l];
                U[3][l] = b2 * P[3][l];
            }
            float Pp[4][4];
#pragma unroll
            for (int i = 0; i < 4; i++)
#pragma unroll
                for (int l = i; l < 4; l++) {
                    Pp[i][l] = (l < 3)
                        ? (U[i][0] * B1[l][0] + U[i][1] * B1[l][1] + U[i][2] * B1[l][2])
                        : (U[i][3] * b2);
                    Pp[l][i] = Pp[i][l];                 // mirror (register alias)
                }
            Pp[0][0] += q[0]; Pp[1][1] += q[1]; Pp[2][2] += q[2]; Pp[3][3] += q[3];

            // ================= regime 2 (rank-1 + diag) =================
            const float s2 = Pp[3][3];
            float v2[9];
#pragma unroll
            for (int o = 0; o < 9; o++) v2[o] = yc[o] - bv[o] * ep[3];
            float vdv2 = 0.0f, tv = 0.0f;
#pragma unroll
            for (int o = 0; o < 9; o++) {
                vdv2 += v2[o] * v2[o] * dinv[o];
                tv   += tb[o] * v2[o];
            }
            const float den  = 1.0f + s2 * g2;
            const float rden = __fdividef(1.0f, den);
            const float ll2 = LLC - 0.5f * (logdetD + __logf(den))
                                  - 0.5f * (vdv2 - s2 * tv * tv * rden);
            const float kv  = tv * rden;
            float p3r[4];
#pragma unroll
            for (int i = 0; i < 4; i++) p3r[i] = Pp[i][3];
            float eta2[4];
#pragma unroll
            for (int i = 0; i < 4; i++) eta2[i] = ep[i] + p3r[i] * kv;
            // optimal-gain identity: P2 = Pp - c2s * p3 p3^T
            const float c2s = g2 * rden;
            float bp[4];
#pragma unroll
            for (int i = 0; i < 4; i++) bp[i] = c2s * p3r[i];
            float P2u[4][4];
#pragma unroll
            for (int i = 0; i < 4; i++)
#pragma unroll
                for (int l = i; l < 4; l++)
                    P2u[i][l] = Pp[i][l] - bp[i] * p3r[l];

            // ================= regime 1 (rank-3 + diag, Woodbury) =================
            float v1[9];
#pragma unroll
            for (int j = 0; j < 3; j++)
#pragma unroll
                for (int k = 0; k < 3; k++)
                    v1[3 * j + k] = yc[3 * j + k] - w[j][k] * ep[j];
            float vdv1 = 0.0f;
#pragma unroll
            for (int o = 0; o < 9; o++) vdv1 += v1[o] * v1[o] * dinv[o];
            float cc[3];
#pragma unroll
            for (int j = 0; j < 3; j++)
                cc[j] = t1[j][0] * v1[3 * j] + t1[j][1] * v1[3 * j + 1] + t1[j][2] * v1[3 * j + 2];

            // M = I + S*diag(g), S = Pp[0:3,0:3]
            const float M00 = 1.0f + Pp[0][0] * g[0], M01 = Pp[0][1] * g[1], M02 = Pp[0][2] * g[2];
            const float M10 = Pp[1][0] * g[0], M11 = 1.0f + Pp[1][1] * g[1], M12 = Pp[1][2] * g[2];
            const float M20 = Pp[2][0] * g[0], M21 = Pp[2][1] * g[1], M22 = 1.0f + Pp[2][2] * g[2];
            const float co00 = M11 * M22 - M12 * M21;
            const float co01 = M12 * M20 - M10 * M22;
            const float co02 = M10 * M21 - M11 * M20;
            const float detM = M00 * co00 + M01 * co01 + M02 * co02;
            const float rdet = __fdividef(1.0f, detM);
            float Mi[3][3];
            Mi[0][0] = co00 * rdet;
            Mi[0][1] = (M02 * M21 - M01 * M22) * rdet;
            Mi[0][2] = (M01 * M12 - M02 * M11) * rdet;
            Mi[1][0] = co01 * rdet;
            Mi[1][1] = (M00 * M22 - M02 * M20) * rdet;
            Mi[1][2] = (M02 * M10 - M00 * M12) * rdet;
            Mi[2][0] = co02 * rdet;
            Mi[2][1] = (M01 * M20 - M00 * M21) * rdet;
            Mi[2][2] = (M00 * M11 - M01 * M10) * rdet;

            // N = M^-1 S
            float Nm[3][3];
#pragma unroll
            for (int i = 0; i < 3; i++)
#pragma unroll
                for (int j2 = 0; j2 < 3; j2++)
                    Nm[i][j2] = Mi[i][0] * Pp[0][j2] + Mi[i][1] * Pp[1][j2] + Mi[i][2] * Pp[2][j2];
            float quadsub = 0.0f;
#pragma unroll
            for (int i = 0; i < 3; i++)
                quadsub += cc[i] * (Nm[i][0] * cc[0] + Nm[i][1] * cc[1] + Nm[i][2] * cc[2]);
            const float ll1 = LLC - 0.5f * (logdetD + __logf(detM))
                                  - 0.5f * (vdv1 - quadsub);

            // K[i, 3j+k] = C[j][i] * t1[j][k],  C = Hr - (N G) Hr
            float Ng[3][3];
#pragma unroll
            for (int j = 0; j < 3; j++)
#pragma unroll
                for (int m = 0; m < 3; m++)
                    Ng[j][m] = Nm[j][m] * g[m];
            float C[3][4];
#pragma unroll
            for (int j = 0; j < 3; j++)
#pragma unroll
                for (int i = 0; i < 4; i++)
                    C[j][i] = Pp[j][i] - (Ng[j][0] * Pp[0][i] + Ng[j][1] * Pp[1][i] + Ng[j][2] * Pp[2][i]);
            float eta1[4];
#pragma unroll
            for (int i = 0; i < 4; i++)
                eta1[i] = ep[i] + C[0][i] * cc[0] + C[1][i] * cc[1] + C[2][i] * cc[2];

            // optimal-gain identity: P1 = Pp - sum_j Cg[j][i] * Pp[j][l]  (upper only)
            float Cg[3][4];
#pragma unroll
            for (int m = 0; m < 3; m++)
#pragma unroll
                for (int i = 0; i < 4; i++)
                    Cg[m][i] = C[m][i] * g[m];
            float P1u[4][4];
#pragma unroll
            for (int i = 0; i < 4; i++)
#pragma unroll
                for (int l = i; l < 4; l++)
                    P1u[i][l] = Pp[i][l]
                              - (Cg[0][i] * Pp[0][l] + Cg[1][i] * Pp[1][l] + Cg[2][i] * Pp[2][l]);

            // ================= IMM mixing (reference EPS arithmetic) =================
            const float e1 = __expf(ll1), e2 = __expf(ll2);
            const float num1 = e1 * (pr1 * p11);
            const float num2 = e2 * (pr1 * (1.0f - p11) + pr2);
            const float marg = num1 + num2 + 1e-9f;
            ll += __logf(marg);
            const float rmarg = __fdividef(1.0f, marg);
            pr1 = num1 * rmarg;
            pr2 = num2 * rmarg;

            float etat[4], d1v[4], d2v[4];
#pragma unroll
            for (int i = 0; i < 4; i++) {
                etat[i] = pr1 * eta1[i] + pr2 * eta2[i];
                d1v[i]  = eta1[i] - etat[i];
                d2v[i]  = eta2[i] - etat[i];
            }
#pragma unroll
            for (int i = 0; i < 4; i++) {
                eta[i] = etat[i];
#pragma unroll
                for (int l = i; l < 4; l++) {
                    const float pt = pr1 * (P1u[i][l] + d1v[i] * d1v[l])
                                   + pr2 * (P2u[i][l] + d2v[i] * d2v[l]);
                    P[i][l] = pt;
                    P[l][i] = pt;
                }
            }

            // ---- outputs ----
            pout[t * 2 + 0] = pr1;
            pout[t * 2 + 1] = pr2;
            const float pe3 = pr2 * etat[3];
#pragma unroll
            for (int j = 0; j < 3; j++)
#pragma unroll
                for (int k = 0; k < 3; k++) {
                    const int o = 3 * j + k;
                    yout[t * 9 + o] = pr1 * (w[j][k] * etat[j]) + bv[o] * pe3;
                }
        }
    }

    // deterministic per-block partial for the NLL
#pragma unroll
    for (int off = 16; off > 0; off >>= 1)
        ll += __shfl_xor_sync(0xffffffffu, ll, off);
    if (threadIdx.x == 0) g_partial[blockIdx.x] = ll;
}

__global__ void nll_reduce_kernel(float* __restrict__ out, int nb)
{
    // one warp, fixed strided order + fixed shuffle tree -> deterministic
    const int t = threadIdx.x;
    float s = 0.0f;
    for (int i = t; i < nb; i += 32) s += g_partial[i];
#pragma unroll
    for (int off = 16; off > 0; off >>= 1)
        s += __shfl_xor_sync(0xffffffffu, s, off);
    if (t == 0) out[0] = -s;
}

extern "C" void kernel_launch(void* const* d_in, const int* in_sizes, int n_in,
                              void* d_out, int out_size)
{
    const float* y     = (const float*)d_in[0];
    const float* B1s1  = (const float*)d_in[1];
    const float* B1s2  = (const float*)d_in[2];
    const float* l1f   = (const float*)d_in[3];
    const float* l2f   = (const float*)d_in[4];
    const float* logq  = (const float*)d_in[5];
    const float* logr  = (const float*)d_in[6];
    const float* gi    = (const float*)d_in[7];
    const float* gcoef = (const float*)d_in[8];

    const int nTot = in_sizes[0] / (NT_ * O_);   // 4096

    float* out   = (float*)d_out;
    float* probs = out + 1;
    float* ypred = out + 1 + (size_t)nTot * NT_ * 2;

    const int grid = (nTot + 31) / 32;           // 128 blocks of 1 warp -> max SM spread
    imm_kf_kernel<<<grid, 32>>>(y, B1s1, B1s2, l1f, l2f, logq, logr, gi, gcoef,
                                probs, ypred, nTot);
    nll_reduce_kernel<<<1, 32>>>(out, grid);
}